// round 13
// baseline (speedup 1.0000x reference)
#include <cuda_runtime.h>
#include <cuda_bf16.h>
#include <cstdint>
#include <limits.h>

#define NPTS 4096
#define DIM  768
#define WD   64
#define KTOP 100
#define NT   528            // triangular 128x128 tiles
#define PADK 24             // hmma smem row stride (bf16)
#define TAU  0.05f

// dynamic smem layout (bytes)
#define OFF_AS   0          // ffma2 As[2][16][132] f32  (16896)
#define OFF_BS   16896      // ffma2 Bs[2][16][132] f32  (16896)
#define OFF_AH   33792      // hmma Ah[128*24] bf16 (6144)
#define OFF_AL   39936
#define OFF_BH   46080
#define OFF_BL   52224
#define OFF_ROWF 58368      // int[128]
#define OFF_COLF 58880
#define OFF_ROWH 59392
#define OFF_COLH 59904
#define OFF_QF   60416
#define OFF_QH   60420
#define SMEM_HY  60448

// scratch (no allocations allowed)
__device__ int            g_counts[NPTS];
__device__ int            g_best;          // packed argmin key: count*4096 + idx
__device__ int            g_q;             // shared tile queue
__device__ float          g_simseed[NPTS];
__device__ int            g_s[NPTS];
__device__ __nv_bfloat16  g_Xh[NPTS * DIM];
__device__ __nv_bfloat16  g_Xl[NPTS * DIM];

// ---------------------------------------------------------------------------
// helpers
// ---------------------------------------------------------------------------
__device__ __forceinline__ void ldsm_x4(uint32_t r[4], uint32_t addr) {
    asm volatile("ldmatrix.sync.aligned.m8n8.x4.shared.b16 {%0,%1,%2,%3}, [%4];"
                 : "=r"(r[0]), "=r"(r[1]), "=r"(r[2]), "=r"(r[3]) : "r"(addr));
}
__device__ __forceinline__ void mma_bf16(float d[4], const uint32_t a[4],
                                         uint32_t b0, uint32_t b1) {
    asm volatile("mma.sync.aligned.m16n8k16.row.col.f32.bf16.bf16.f32 "
                 "{%0,%1,%2,%3},{%4,%5,%6,%7},{%8,%9},{%0,%1,%2,%3};"
                 : "+f"(d[0]), "+f"(d[1]), "+f"(d[2]), "+f"(d[3])
                 : "r"(a[0]), "r"(a[1]), "r"(a[2]), "r"(a[3]), "r"(b0), "r"(b1));
}
__device__ __forceinline__ float exact_dot(const float* __restrict__ X, int gi, int gj) {
    const float4* a = (const float4*)(X + (size_t)gi * DIM);
    const float4* b = (const float4*)(X + (size_t)gj * DIM);
    float s = 0.0f;
    #pragma unroll 4
    for (int d = 0; d < DIM / 4; d++) {
        float4 u = a[d], w = b[d];
        s += u.x * w.x + u.y * w.y + u.z * w.z + u.w * w.w;
    }
    return s;
}
__device__ __forceinline__ void decode_tile(int t, int& bi, int& bj) {
    bi = (int)((65.0 - sqrt(4225.0 - 8.0 * (double)t)) * 0.5);
    while (bi * (65 - bi) / 2 > t) bi--;
    while ((bi + 1) * (64 - bi) / 2 <= t) bi++;
    bj = bi + (t - bi * (65 - bi) / 2);
}
__device__ __forceinline__ int blend_seed(int key, const int* __restrict__ attn) {
    int idx = key & 4095;
    int r = idx >> 6, c = idx & 63;
    int tr = r + attn[0];
    int tc = c + attn[1];
    int rr = tr >> 1; if (tr & 1) rr += (rr & 1);
    int cc = tc >> 1; if (tc & 1) cc += (cc & 1);
    return rr * WD + cc;
}

// ---------------------------------------------------------------------------
// 0) fp32 -> (bf16 hi, lo) split + global init (fused)
// ---------------------------------------------------------------------------
__global__ void convert_split(const float* __restrict__ X) {
    int i = blockIdx.x * blockDim.x + threadIdx.x;   // one float4 per thread
    if (i < NPTS) g_counts[i] = 1;                   // diagonal always >= 0
    if (i == 0) { g_best = INT_MAX; g_q = 0; }
    float4 v = ((const float4*)X)[i];
    __nv_bfloat16 hx = __float2bfloat16_rn(v.x);
    __nv_bfloat16 hy = __float2bfloat16_rn(v.y);
    __nv_bfloat16 hz = __float2bfloat16_rn(v.z);
    __nv_bfloat16 hw = __float2bfloat16_rn(v.w);
    __nv_bfloat162* oh = (__nv_bfloat162*)g_Xh;
    __nv_bfloat162* ol = (__nv_bfloat162*)g_Xl;
    oh[2 * i + 0] = __nv_bfloat162(hx, hy);
    oh[2 * i + 1] = __nv_bfloat162(hz, hw);
    ol[2 * i + 0] = __floats2bfloat162_rn(v.x - __bfloat162float(hx),
                                          v.y - __bfloat162float(hy));
    ol[2 * i + 1] = __floats2bfloat162_rn(v.z - __bfloat162float(hz),
                                          v.w - __bfloat162float(hw));
}

#define BAR1() asm volatile("bar.sync 1, 128;" ::: "memory")
#define BAR2() asm volatile("bar.sync 2, 128;" ::: "memory")

// ---------------------------------------------------------------------------
// FFMA2 engine: warps 0-3. Exact fp32, packed fma.rn.f32x2, 16Mx8N per thread.
// ---------------------------------------------------------------------------
__device__ __forceinline__ void ffma2_part(const float* __restrict__ X, char* sm, int tid) {
    float* As = (float*)(sm + OFF_AS);
    float* Bs = (float*)(sm + OFF_BS);
    int* rowS = (int*)(sm + OFF_ROWF);
    int* colS = (int*)(sm + OFF_COLF);
    int* qs   = (int*)(sm + OFF_QF);
    int tx = tid & 15, ty = tid >> 4;     // tx: 8 cols, ty: 16 rows

    while (true) {
        if (tid == 0) *qs = atomicAdd(&g_q, 1);
        BAR1();
        int t = *qs;
        BAR1();
        if (t >= NT) return;
        int bi, bj; decode_tile(t, bi, bj);
        int i0 = bi * 128, j0 = bj * 128;
        bool diag = (bi == bj);

        unsigned long long acc2[8][8];
        #pragma unroll
        for (int p = 0; p < 8; p++)
            #pragma unroll
            for (int n = 0; n < 8; n++) acc2[p][n] = 0ull;

        const float4* ga = (const float4*)(X + (size_t)(i0 + tid) * DIM);
        const float4* gb = (const float4*)(X + (size_t)(j0 + tid) * DIM);
        float4 ra[4], rb[4];

#define LDGT(kt) { _Pragma("unroll") for (int q = 0; q < 4; q++) { \
            ra[q] = ga[(kt) * 4 + q]; rb[q] = gb[(kt) * 4 + q]; } }
#define STST(buf) { _Pragma("unroll") for (int q = 0; q < 4; q++) { \
            float* ab = &As[((buf) * 16 + 4 * q) * 132 + tid]; \
            float* bb = &Bs[((buf) * 16 + 4 * q) * 132 + tid]; \
            ab[0] = ra[q].x; ab[132] = ra[q].y; ab[264] = ra[q].z; ab[396] = ra[q].w; \
            bb[0] = rb[q].x; bb[132] = rb[q].y; bb[264] = rb[q].z; bb[396] = rb[q].w; } }

        LDGT(0); STST(0);
        BAR1();

        for (int kt = 0; kt < 48; kt++) {
            int buf = kt & 1;
            if (kt + 1 < 48) LDGT(kt + 1);
            #pragma unroll
            for (int k = 0; k < 16; k++) {
                const float* arow = &As[(buf * 16 + k) * 132];
                const float* brow = &Bs[(buf * 16 + k) * 132];
                const ulonglong2* ap = (const ulonglong2*)(arow + ty * 16);
                ulonglong2 a0 = ap[0], a1 = ap[1], a2 = ap[2], a3 = ap[3];
                unsigned long long av[8] = {a0.x, a0.y, a1.x, a1.y, a2.x, a2.y, a3.x, a3.y};
                const float4* bp = (const float4*)(brow + tx * 8);
                float4 b0 = bp[0], b1 = bp[1];
                float bf[8] = {b0.x, b0.y, b0.z, b0.w, b1.x, b1.y, b1.z, b1.w};
                unsigned long long b2[8];
                #pragma unroll
                for (int n = 0; n < 8; n++)
                    asm("mov.b64 %0, {%1, %2};" : "=l"(b2[n]) : "f"(bf[n]), "f"(bf[n]));
                #pragma unroll
                for (int p = 0; p < 8; p++)
                    #pragma unroll
                    for (int n = 0; n < 8; n++)
                        asm("fma.rn.f32x2 %0, %1, %2, %0;"
                            : "+l"(acc2[p][n]) : "l"(av[p]), "l"(b2[n]));
            }
            if (kt + 1 < 48) STST(buf ^ 1);
            BAR1();
        }
#undef LDGT
#undef STST

        // epilogue
        rowS[tid] = 0; colS[tid] = 0;
        BAR1();
        int rc[16], cc[8];
        #pragma unroll
        for (int m = 0; m < 16; m++) rc[m] = 0;
        #pragma unroll
        for (int n = 0; n < 8; n++) cc[n] = 0;
        #pragma unroll
        for (int p = 0; p < 8; p++) {
            #pragma unroll
            for (int n = 0; n < 8; n++) {
                unsigned long long a = acc2[p][n];
                float vlo = __uint_as_float((unsigned)(a & 0xffffffffull));
                float vhi = __uint_as_float((unsigned)(a >> 32));
                int gj = j0 + tx * 8 + n;
                int gi = i0 + ty * 16 + 2 * p;
                int clo = (vlo >= 0.0f) && (!diag || gj > gi);
                int chi = (vhi >= 0.0f) && (!diag || gj > gi + 1);
                rc[2 * p] += clo; rc[2 * p + 1] += chi;
                cc[n] += clo + chi;
            }
        }
        #pragma unroll
        for (int m = 0; m < 16; m++) atomicAdd(&rowS[ty * 16 + m], rc[m]);
        #pragma unroll
        for (int n = 0; n < 8; n++) atomicAdd(&colS[tx * 8 + n], cc[n]);
        BAR1();
        if (rowS[tid]) atomicAdd(&g_counts[i0 + tid], rowS[tid]);
        if (colS[tid]) atomicAdd(&g_counts[j0 + tid], colS[tid]);
        BAR1();
    }
}

// ---------------------------------------------------------------------------
// HMMA engine: warps 4-7. 3-pass bf16 (hh+hl+lh) + exact repair. 32x128/warp.
// ---------------------------------------------------------------------------
__device__ __forceinline__ void hmma_part(const float* __restrict__ X, char* sm, int h) {
    uint32_t smadr = (uint32_t)__cvta_generic_to_shared(sm);
    int* rowS = (int*)(sm + OFF_ROWH);
    int* colS = (int*)(sm + OFF_COLH);
    int* qs   = (int*)(sm + OFF_QH);
    int warp = h >> 5, lane = h & 31;

    int rowA = lane & 15, koffA = (lane >> 4) * 8;
    int grp = lane >> 3;
    int nB = ((grp >> 1) * 8) + (lane & 7);
    int koffB = (grp & 1) * 8;
    uint32_t aH[2], aL[2];
    #pragma unroll
    for (int im = 0; im < 2; im++) {
        uint32_t off = (uint32_t)(((warp * 32 + im * 16 + rowA) * PADK + koffA) * 2);
        aH[im] = smadr + OFF_AH + off;
        aL[im] = smadr + OFF_AL + off;
    }
    uint32_t bHb = smadr + OFF_BH + (uint32_t)((nB * PADK + koffB) * 2);
    uint32_t bLb = smadr + OFF_BL + (uint32_t)((nB * PADK + koffB) * 2);

    const uint4* gxh = (const uint4*)g_Xh;
    const uint4* gxl = (const uint4*)g_Xl;
    uint32_t sA = (uint32_t)(h * 48);     // byte offset of row h in each array

    while (true) {
        if (h == 0) *qs = atomicAdd(&g_q, 1);
        BAR2();
        int t = *qs;
        BAR2();
        if (t >= NT) return;
        int bi, bj; decode_tile(t, bi, bj);
        int i0 = bi * 128, j0 = bj * 128;
        bool diag = (bi == bj);

        float acc[2][16][4];
        #pragma unroll
        for (int im = 0; im < 2; im++)
            #pragma unroll
            for (int jn = 0; jn < 16; jn++)
                #pragma unroll
                for (int e = 0; e < 4; e++) acc[im][jn][e] = 0.0f;

        int arow = (i0 + h) * (DIM / 8);
        int brow = (j0 + h) * (DIM / 8);
        uint4 pa0, pa1, pl0, pl1, pb0, pb1, pm0, pm1;

#define HLDG(kt) { int o = (kt) * 2; \
            pa0 = gxh[arow + o]; pa1 = gxh[arow + o + 1]; \
            pl0 = gxl[arow + o]; pl1 = gxl[arow + o + 1]; \
            pb0 = gxh[brow + o]; pb1 = gxh[brow + o + 1]; \
            pm0 = gxl[brow + o]; pm1 = gxl[brow + o + 1]; }
#define HSTS() { \
            *(uint4*)(sm + OFF_AH + sA) = pa0; *(uint4*)(sm + OFF_AH + sA + 16) = pa1; \
            *(uint4*)(sm + OFF_AL + sA) = pl0; *(uint4*)(sm + OFF_AL + sA + 16) = pl1; \
            *(uint4*)(sm + OFF_BH + sA) = pb0; *(uint4*)(sm + OFF_BH + sA + 16) = pb1; \
            *(uint4*)(sm + OFF_BL + sA) = pm0; *(uint4*)(sm + OFF_BL + sA + 16) = pm1; }

        HLDG(0); HSTS();
        BAR2();

        for (int kt = 0; kt < 48; kt++) {
            if (kt + 1 < 48) HLDG(kt + 1);
            uint32_t ah[2][4], al[2][4];
            ldsm_x4(ah[0], aH[0]); ldsm_x4(ah[1], aH[1]);
            ldsm_x4(al[0], aL[0]); ldsm_x4(al[1], aL[1]);
            #pragma unroll
            for (int jb = 0; jb < 8; jb++) {
                uint32_t bh[4], bl[4];
                ldsm_x4(bh, bHb + jb * 768);
                ldsm_x4(bl, bLb + jb * 768);
                #pragma unroll
                for (int im = 0; im < 2; im++)
                    #pragma unroll
                    for (int jh = 0; jh < 2; jh++) {
                        int o = jh * 2;
                        float* d = acc[im][2 * jb + jh];
                        mma_bf16(d, ah[im], bh[o], bh[o + 1]);
                        mma_bf16(d, ah[im], bl[o], bl[o + 1]);
                        mma_bf16(d, al[im], bh[o], bh[o + 1]);
                    }
            }
            BAR2();
            if (kt + 1 < 48) HSTS();
            BAR2();
        }
#undef HLDG
#undef HSTS

        // epilogue: signs (+ rare exact repair), counts
        rowS[h] = 0; colS[h] = 0;
        BAR2();
        int rc[4] = {0, 0, 0, 0};
        int cc[32];
        #pragma unroll
        for (int q = 0; q < 32; q++) cc[q] = 0;
        int rb0 = warp * 32 + (lane >> 2);
        int cb0 = (lane & 3) * 2;
        #pragma unroll
        for (int im = 0; im < 2; im++) {
            #pragma unroll
            for (int jn = 0; jn < 16; jn++) {
                #pragma unroll
                for (int e4 = 0; e4 < 4; e4++) {
                    int h8 = e4 >> 1, e = e4 & 1;
                    int gi = i0 + rb0 + im * 16 + h8 * 8;
                    int gj = j0 + jn * 8 + cb0 + e;
                    if (diag && gj <= gi) continue;
                    float v = acc[im][jn][e4];
                    int bit;
                    if (fabsf(v) >= TAU) bit = (v >= 0.0f);
                    else                 bit = (exact_dot(X, gi, gj) >= 0.0f);
                    rc[im * 2 + h8] += bit;
                    cc[jn * 2 + e] += bit;
                }
            }
        }
        #pragma unroll
        for (int im = 0; im < 2; im++)
            #pragma unroll
            for (int h8 = 0; h8 < 2; h8++)
                atomicAdd(&rowS[rb0 + im * 16 + h8 * 8], rc[im * 2 + h8]);
        #pragma unroll
        for (int jn = 0; jn < 16; jn++)
            #pragma unroll
            for (int e = 0; e < 2; e++)
                atomicAdd(&colS[jn * 8 + cb0 + e], cc[jn * 2 + e]);
        BAR2();
        if (rowS[h]) atomicAdd(&g_counts[i0 + h], rowS[h]);
        if (colS[h]) atomicAdd(&g_counts[j0 + h], colS[h]);
        BAR2();
    }
}

// ---------------------------------------------------------------------------
// 1) persistent dual-pipe GEMM: warps 0-3 FFMA2 (fma pipe), 4-7 HMMA (tensor)
// ---------------------------------------------------------------------------
__global__ __launch_bounds__(256)
void hybrid_gemm(const float* __restrict__ X) {
    extern __shared__ char sm[];
    int tid = threadIdx.x;
    if (tid < 128) ffma2_part(X, sm, tid);
    else           hmma_part(X, sm, tid - 128);
}

// ---------------------------------------------------------------------------
// 2) grid-wide argmin of counts via packed key atomicMin (first occurrence)
// ---------------------------------------------------------------------------
__global__ void argmin_kernel() {
    int i = blockIdx.x * blockDim.x + threadIdx.x;   // 4096 threads
    int key = g_counts[i] * 4096 + i;
    #pragma unroll
    for (int o = 16; o > 0; o >>= 1)
        key = min(key, __shfl_xor_sync(0xffffffffu, key, o));
    if ((threadIdx.x & 31) == 0) atomicMin(&g_best, key);
}

// ---------------------------------------------------------------------------
// 3) sim[seed][j] for all j + initial mask. warp per j, float4 loads.
// ---------------------------------------------------------------------------
__global__ void seedrow_kernel(const float* __restrict__ X,
                               const int* __restrict__ attn) {
    int gwarp = (blockIdx.x * blockDim.x + threadIdx.x) >> 5;
    int lane  = threadIdx.x & 31;
    if (gwarp >= NPTS) return;
    int seed = blend_seed(g_best, attn);
    const float4* xs = (const float4*)(X + (size_t)seed * DIM);
    const float4* xj = (const float4*)(X + (size_t)gwarp * DIM);
    float p = 0.0f;
    #pragma unroll
    for (int q = 0; q < 6; q++) {
        float4 u = xs[lane + 32 * q], w = xj[lane + 32 * q];
        p += u.x * w.x + u.y * w.y + u.z * w.z + u.w * w.w;
    }
    #pragma unroll
    for (int o = 16; o > 0; o >>= 1) p += __shfl_down_sync(0xffffffffu, p, o);
    if (lane == 0) {
        g_simseed[gwarp] = p;
        g_s[gwarp] = (p >= 0.0f) ? 1 : 0;
    }
}

// ---------------------------------------------------------------------------
// 4) top-100 via bitonic sort on packed 64-bit keys
// ---------------------------------------------------------------------------
__device__ __forceinline__ unsigned ford(float v) {   // monotonic float->uint
    unsigned u = __float_as_uint(v);
    return (u & 0x80000000u) ? ~u : (u | 0x80000000u);
}
__global__ void topk_kernel(const int* __restrict__ attn) {
    __shared__ unsigned long long sk[NPTS];
    int tid = threadIdx.x;   // 1024 threads
    int seed = blend_seed(g_best, attn);
    for (int i = tid; i < NPTS; i += 1024)
        sk[i] = ((unsigned long long)ford(g_simseed[i]) << 32)
              | (unsigned)(NPTS - 1 - i);
    __syncthreads();
    for (int k = 2; k <= NPTS; k <<= 1) {
        for (int j = k >> 1; j > 0; j >>= 1) {
            for (int i = tid; i < NPTS; i += 1024) {
                int ixj = i ^ j;
                if (ixj > i) {
                    unsigned long long k1 = sk[i], k2 = sk[ixj];
                    bool g = (k1 < k2);
                    bool dirDesc = ((i & k) == 0);
                    if (g == dirDesc) { sk[i] = k2; sk[ixj] = k1; }
                }
            }
            __syncthreads();
        }
    }
    unsigned long long k99 = sk[KTOP - 1];
    for (int i = tid; i < NPTS; i += 1024) {
        int s = g_s[i];
        if (i == seed) s = 1;
        unsigned long long ki = ((unsigned long long)ford(g_simseed[i]) << 32)
                              | (unsigned)(NPTS - 1 - i);
        g_s[i] = (ki >= k99) ? s : 0;
    }
}

// ---------------------------------------------------------------------------
// 5) sequential expansion, single warp, float4 loads, register accumulator.
// ---------------------------------------------------------------------------
__global__ void scan_kernel(const float* __restrict__ X) {
    __shared__ int list[KTOP + 32];
    int lane = threadIdx.x;   // 32 threads

    int cnt = 0;
    for (int c = 0; c < NPTS / 32; c++) {
        int idx = c * 32 + lane;
        int val = g_s[idx];
        unsigned m = __ballot_sync(0xffffffffu, val != 0);
        if (val) {
            int pos = cnt + __popc(m & ((1u << lane) - 1));
            if (pos < KTOP + 32) list[pos] = idx;
        }
        cnt += __popc(m);
    }
    int na = (cnt < KTOP + 32) ? cnt : (KTOP + 32);
    __syncwarp();

    float4 v4[6];
    #pragma unroll
    for (int q = 0; q < 6; q++) v4[q] = make_float4(0.f, 0.f, 0.f, 0.f);
    for (int l = 0; l < na; l++) {
        const float4* x = (const float4*)(X + (size_t)list[l] * DIM);
        #pragma unroll
        for (int q = 0; q < 6; q++) {
            float4 u = x[lane + 32 * q];
            v4[q].x += u.x; v4[q].y += u.y; v4[q].z += u.z; v4[q].w += u.w;
        }
    }

    for (int l = 0; l < na; l++) {
        int i = list[l];
        const float4* x = (const float4*)(X + (size_t)i * DIM);
        float4 xr[6];
        float dot = 0.0f;
        #pragma unroll
        for (int q = 0; q < 6; q++) {
            xr[q] = x[lane + 32 * q];
            dot += xr[q].x * v4[q].x + xr[q].y * v4[q].y
                 + xr[q].z * v4[q].z + xr[q].w * v4[q].w;
        }
        #pragma unroll
        for (int o = 16; o > 0; o >>= 1) dot += __shfl_xor_sync(0xffffffffu, dot, o);
        if (dot <= 0.0f) {
            if (lane == 0) g_s[i] = 0;
            #pragma unroll
            for (int q = 0; q < 6; q++) {
                v4[q].x -= xr[q].x; v4[q].y -= xr[q].y;
                v4[q].z -= xr[q].z; v4[q].w -= xr[q].w;
            }
        }
    }
}

// ---------------------------------------------------------------------------
// 6) 8-connected components: in-place min-label propagation to fixpoint.
// ---------------------------------------------------------------------------
__global__ void cc_kernel(float* __restrict__ outp) {
    __shared__ int lab[66 * 66];
    __shared__ int changed;
    const int BIG = NPTS + 1;
    int tid = threadIdx.x;   // 1024 threads

    for (int p = tid; p < 66 * 66; p += 1024) lab[p] = BIG;
    __syncthreads();

    int fgp[4], pos[4];
    #pragma unroll
    for (int q = 0; q < 4; q++) {
        int p = tid + q * 1024;
        int r = p >> 6, c = p & 63;
        pos[q] = (r + 1) * 66 + (c + 1);
        fgp[q] = g_s[p];
        lab[pos[q]] = fgp[q] ? (p + 1) : BIG;
    }
    __syncthreads();

    while (true) {
        if (tid == 0) changed = 0;
        __syncthreads();
        int lc = 0;
        #pragma unroll
        for (int q = 0; q < 4; q++) {
            if (fgp[q]) {
                int pp = pos[q];
                int m = lab[pp];
                m = min(m, lab[pp - 67]); m = min(m, lab[pp - 66]); m = min(m, lab[pp - 65]);
                m = min(m, lab[pp - 1]);                            m = min(m, lab[pp + 1]);
                m = min(m, lab[pp + 65]); m = min(m, lab[pp + 66]); m = min(m, lab[pp + 67]);
                if (m < lab[pp]) { lab[pp] = m; lc = 1; }
            }
        }
        if (lc) changed = 1;
        __syncthreads();
        int done = !changed;
        __syncthreads();
        if (done) break;
    }

    #pragma unroll
    for (int q = 0; q < 4; q++) {
        int p = tid + q * 1024;
        outp[p] = fgp[q] ? (float)lab[pos[q]] : 0.0f;
    }
}

// ---------------------------------------------------------------------------
extern "C" void kernel_launch(void* const* d_in, const int* in_sizes, int n_in,
                              void* d_out, int out_size) {
    const float* X;
    const int*   attn;
    if (n_in >= 2 && in_sizes[0] == 2) {
        attn = (const int*)d_in[0];
        X    = (const float*)d_in[1];
    } else {
        X    = (const float*)d_in[0];
        attn = (const int*)d_in[1];
    }
    float* outp = (float*)d_out;

    cudaFuncSetAttribute(hybrid_gemm, cudaFuncAttributeMaxDynamicSharedMemorySize, SMEM_HY);

    convert_split<<<(NPTS * DIM / 4) / 256, 256>>>(X);
    hybrid_gemm<<<148, 256, SMEM_HY>>>(X);
    argmin_kernel<<<16, 256>>>();
    seedrow_kernel<<<NPTS / 8, 256>>>(X, attn);
    topk_kernel<<<1, 1024>>>(attn);
    scan_kernel<<<1, 32>>>(X);
    cc_kernel<<<1, 1024>>>(outp);
}

// round 14
// speedup vs baseline: 1.0823x; 1.0823x over previous
#include <cuda_runtime.h>
#include <cuda_bf16.h>
#include <cstdint>
#include <limits.h>

#define NPTS 4096
#define DIM  768
#define WD   64
#define KTOP 100
#define NT   528            // triangular 128x128 tiles
#define BM   128
#define BK   16
#define PADK 24
#define TBA  (128 * PADK * 2)       // 6144 bytes per hmma tile array
#define TAU  0.05f
#define SMEM_DYN 49152              // max(ffma2 33792, hmma 49152)

// scratch (no allocations allowed)
__device__ int            g_counts[NPTS];
__device__ int            g_best;          // packed argmin key: count*4096 + idx
__device__ int            g_q;             // shared tile queue
__device__ float          g_simseed[NPTS];
__device__ int            g_s[NPTS];
__device__ __nv_bfloat16  g_Xh[NPTS * DIM];
__device__ __nv_bfloat16  g_Xl[NPTS * DIM];

// ---------------------------------------------------------------------------
// helpers
// ---------------------------------------------------------------------------
__device__ __forceinline__ void ldsm_x4(uint32_t r[4], uint32_t addr) {
    asm volatile("ldmatrix.sync.aligned.m8n8.x4.shared.b16 {%0,%1,%2,%3}, [%4];"
                 : "=r"(r[0]), "=r"(r[1]), "=r"(r[2]), "=r"(r[3]) : "r"(addr));
}
__device__ __forceinline__ void mma_bf16(float d[4], const uint32_t a[4],
                                         uint32_t b0, uint32_t b1) {
    asm volatile("mma.sync.aligned.m16n8k16.row.col.f32.bf16.bf16.f32 "
                 "{%0,%1,%2,%3},{%4,%5,%6,%7},{%8,%9},{%0,%1,%2,%3};"
                 : "+f"(d[0]), "+f"(d[1]), "+f"(d[2]), "+f"(d[3])
                 : "r"(a[0]), "r"(a[1]), "r"(a[2]), "r"(a[3]), "r"(b0), "r"(b1));
}
__device__ __forceinline__ float exact_dot(const float* __restrict__ X, int gi, int gj) {
    const float4* a = (const float4*)(X + (size_t)gi * DIM);
    const float4* b = (const float4*)(X + (size_t)gj * DIM);
    float s = 0.0f;
    #pragma unroll 4
    for (int d = 0; d < DIM / 4; d++) {
        float4 u = a[d], w = b[d];
        s += u.x * w.x + u.y * w.y + u.z * w.z + u.w * w.w;
    }
    return s;
}
__device__ __forceinline__ void decode_tile(int t, int& bi, int& bj) {
    bi = (int)((65.0 - sqrt(4225.0 - 8.0 * (double)t)) * 0.5);
    while (bi * (65 - bi) / 2 > t) bi--;
    while ((bi + 1) * (64 - bi) / 2 <= t) bi++;
    bj = bi + (t - bi * (65 - bi) / 2);
}
__device__ __forceinline__ int blend_seed(int key, const int* __restrict__ attn) {
    int idx = key & 4095;
    int r = idx >> 6, c = idx & 63;
    int tr = r + attn[0];
    int tc = c + attn[1];
    int rr = tr >> 1; if (tr & 1) rr += (rr & 1);
    int cc = tc >> 1; if (tc & 1) cc += (cc & 1);
    return rr * WD + cc;
}

// ---------------------------------------------------------------------------
// 0) fp32 -> (bf16 hi, lo) split + global init (fused)
// ---------------------------------------------------------------------------
__global__ void convert_split(const float* __restrict__ X) {
    int i = blockIdx.x * blockDim.x + threadIdx.x;   // one float4 per thread
    if (i < NPTS) g_counts[i] = 1;                   // diagonal always >= 0
    if (i == 0) { g_best = INT_MAX; g_q = 0; }
    float4 v = ((const float4*)X)[i];
    __nv_bfloat16 hx = __float2bfloat16_rn(v.x);
    __nv_bfloat16 hy = __float2bfloat16_rn(v.y);
    __nv_bfloat16 hz = __float2bfloat16_rn(v.z);
    __nv_bfloat16 hw = __float2bfloat16_rn(v.w);
    __nv_bfloat162* oh = (__nv_bfloat162*)g_Xh;
    __nv_bfloat162* ol = (__nv_bfloat162*)g_Xl;
    oh[2 * i + 0] = __nv_bfloat162(hx, hy);
    oh[2 * i + 1] = __nv_bfloat162(hz, hw);
    ol[2 * i + 0] = __floats2bfloat162_rn(v.x - __bfloat162float(hx),
                                          v.y - __bfloat162float(hy));
    ol[2 * i + 1] = __floats2bfloat162_rn(v.z - __bfloat162float(hz),
                                          v.w - __bfloat162float(hw));
}

// ---------------------------------------------------------------------------
// FFMA2 engine (whole CTA): exact round-12 tiling, queue-fed persistent loop.
// ---------------------------------------------------------------------------
__device__ void ffma2_engine(const float* __restrict__ X, char* sm) {
    float* As = (float*)sm;             // [2*16*132] f32
    float* Bs = (float*)(sm + 16896);
    __shared__ int rowSum[BM], colSum[BM], qs;

    int tid = threadIdx.x;
    int tx = tid & 15, ty = tid >> 4;
    int lrow = tid >> 1;
    int lq4  = (tid & 1) * 8;

    while (true) {
        if (tid == 0) qs = atomicAdd(&g_q, 1);
        __syncthreads();
        int t = qs;
        if (t >= NT) return;
        int bi, bj; decode_tile(t, bi, bj);
        int i0 = bi * BM, j0 = bj * BM;
        bool diag = (bi == bj);

        unsigned long long acc2[4][8];
        #pragma unroll
        for (int p = 0; p < 4; p++)
            #pragma unroll
            for (int n = 0; n < 8; n++) acc2[p][n] = 0ull;

        float4 ra0, ra1, rb0, rb1;
        const float* abase = X + (size_t)(i0 + lrow) * DIM + lq4;
        const float* bbase = X + (size_t)(j0 + lrow) * DIM + lq4;

#define LDG_TILE(kt) {                                         \
        const float* ap = abase + (kt) * BK;                   \
        const float* bp = bbase + (kt) * BK;                   \
        ra0 = *(const float4*)(ap);  ra1 = *(const float4*)(ap + 4); \
        rb0 = *(const float4*)(bp);  rb1 = *(const float4*)(bp + 4); }

#define STS_TILE(buf) { _Pragma("unroll") for (int e = 0; e < 4; e++) { \
        As[((buf) * 16 + lq4 + e) * 132 + lrow]     = (&ra0.x)[e];      \
        As[((buf) * 16 + lq4 + 4 + e) * 132 + lrow] = (&ra1.x)[e];      \
        Bs[((buf) * 16 + lq4 + e) * 132 + lrow]     = (&rb0.x)[e];      \
        Bs[((buf) * 16 + lq4 + 4 + e) * 132 + lrow] = (&rb1.x)[e]; } }

        LDG_TILE(0);
        STS_TILE(0);
        __syncthreads();

        for (int kt = 0; kt < 48; kt++) {
            int buf = kt & 1;
            if (kt + 1 < 48) LDG_TILE(kt + 1);

            #pragma unroll
            for (int k = 0; k < BK; k++) {
                const float* arow = &As[(buf * 16 + k) * 132];
                const float* brow = &Bs[(buf * 16 + k) * 132];
                const ulonglong2* ap = (const ulonglong2*)(arow + ty * 8);
                ulonglong2 a01 = ap[0], a23 = ap[1];
                unsigned long long av[4] = {a01.x, a01.y, a23.x, a23.y};
                const float4* bp = (const float4*)(brow + tx * 8);
                float4 b0 = bp[0], b1 = bp[1];
                float bf[8] = {b0.x, b0.y, b0.z, b0.w, b1.x, b1.y, b1.z, b1.w};
                unsigned long long b2[8];
                #pragma unroll
                for (int n = 0; n < 8; n++)
                    asm("mov.b64 %0, {%1, %2};" : "=l"(b2[n]) : "f"(bf[n]), "f"(bf[n]));
                #pragma unroll
                for (int p = 0; p < 4; p++)
                    #pragma unroll
                    for (int n = 0; n < 8; n++)
                        asm("fma.rn.f32x2 %0, %1, %2, %0;"
                            : "+l"(acc2[p][n]) : "l"(av[p]), "l"(b2[n]));
            }

            if (kt + 1 < 48) STS_TILE(buf ^ 1);
            __syncthreads();
        }
#undef LDG_TILE
#undef STS_TILE

        if (tid < BM) { rowSum[tid] = 0; colSum[tid] = 0; }
        __syncthreads();

        int rcnt[8], ccnt[8];
        #pragma unroll
        for (int m = 0; m < 8; m++) { rcnt[m] = 0; ccnt[m] = 0; }

        #pragma unroll
        for (int p = 0; p < 4; p++) {
            #pragma unroll
            for (int n = 0; n < 8; n++) {
                unsigned long long a = acc2[p][n];
                float vlo = __uint_as_float((unsigned)(a & 0xffffffffull));
                float vhi = __uint_as_float((unsigned)(a >> 32));
                int gj = j0 + tx * 8 + n;
                int gilo = i0 + ty * 8 + 2 * p;
                int clo = (vlo >= 0.0f) && (!diag || gj > gilo);
                int chi = (vhi >= 0.0f) && (!diag || gj > gilo + 1);
                rcnt[2 * p]     += clo;
                rcnt[2 * p + 1] += chi;
                ccnt[n] += clo + chi;
            }
        }
        #pragma unroll
        for (int m = 0; m < 8; m++) atomicAdd(&rowSum[ty * 8 + m], rcnt[m]);
        #pragma unroll
        for (int n = 0; n < 8; n++) atomicAdd(&colSum[tx * 8 + n], ccnt[n]);
        __syncthreads();

        if (tid < BM) {
            if (rowSum[tid]) atomicAdd(&g_counts[i0 + tid], rowSum[tid]);
            if (colSum[tid]) atomicAdd(&g_counts[j0 + tid], colSum[tid]);
        }
        __syncthreads();
    }
}

// ---------------------------------------------------------------------------
// HMMA engine (whole CTA): exact round-10 tiling (8 warps, 32x64 warp tile,
// double-buffered, 1 sync/k-step, 3-pass bf16 + exact repair), queue-fed.
// ---------------------------------------------------------------------------
__device__ void hmma_engine(const float* __restrict__ X, char* sm) {
    __shared__ int rowSum[BM], colSum[BM], qs;
    uint32_t smadr = (uint32_t)__cvta_generic_to_shared(sm);

    int tid  = threadIdx.x;
    int warp = tid >> 5, lane = tid & 31;
    int wm = warp & 3;          // M group
    int wn = warp >> 2;         // N group

    int lrow = tid >> 1, lhalf = tid & 1;
    uint32_t stoff = (uint32_t)((lrow * PADK + lhalf * 8) * 2);

    int rowA  = lane & 15;
    int koffA = (lane >> 4) * 8;
    int grp   = lane >> 3;
    int nB    = ((grp >> 1) * 8) + (lane & 7);
    int koffB = (grp & 1) * 8;

    uint32_t aAddrH[2], aAddrL[2], bAddrH[4], bAddrL[4];
    #pragma unroll
    for (int im = 0; im < 2; im++) {
        uint32_t off = ((wm * 32 + im * 16 + rowA) * PADK + koffA) * 2;
        aAddrH[im] = smadr + off;
        aAddrL[im] = smadr + TBA + off;
    }
    #pragma unroll
    for (int jb = 0; jb < 4; jb++) {
        uint32_t off = ((wn * 64 + jb * 16 + nB) * PADK + koffB) * 2;
        bAddrH[jb] = smadr + 2 * TBA + off;
        bAddrL[jb] = smadr + 3 * TBA + off;
    }
    const uint32_t bufBytes = 4 * TBA;

    while (true) {
        if (tid == 0) qs = atomicAdd(&g_q, 1);
        __syncthreads();
        int t = qs;
        if (t >= NT) return;
        int bi, bj; decode_tile(t, bi, bj);
        int i0 = bi * BM, j0 = bj * BM;
        bool diag = (bi == bj);

        float acc[2][8][4];
        #pragma unroll
        for (int im = 0; im < 2; im++)
            #pragma unroll
            for (int jn = 0; jn < 8; jn++)
                #pragma unroll
                for (int e = 0; e < 4; e++) acc[im][jn][e] = 0.0f;

        const uint4* gah = (const uint4*)(g_Xh + (size_t)(i0 + lrow) * DIM);
        const uint4* gal = (const uint4*)(g_Xl + (size_t)(i0 + lrow) * DIM);
        const uint4* gbh = (const uint4*)(g_Xh + (size_t)(j0 + lrow) * DIM);
        const uint4* gbl = (const uint4*)(g_Xl + (size_t)(j0 + lrow) * DIM);

        uint4 rah, ral, rbh, rbl;
        rah = gah[lhalf]; ral = gal[lhalf]; rbh = gbh[lhalf]; rbl = gbl[lhalf];
        *(uint4*)(sm + stoff)           = rah;
        *(uint4*)(sm + TBA + stoff)     = ral;
        *(uint4*)(sm + 2 * TBA + stoff) = rbh;
        *(uint4*)(sm + 3 * TBA + stoff) = rbl;
        __syncthreads();

        for (int kt = 0; kt < 48; kt++) {
            int b = kt & 1;
            if (kt + 1 < 48) {
                int o = (kt + 1) * 2 + lhalf;
                rah = gah[o]; ral = gal[o]; rbh = gbh[o]; rbl = gbl[o];
            }

            uint32_t ah[2][4], al[2][4], bh[4][4], bl[4][4];
            uint32_t bo = b * bufBytes;
            #pragma unroll
            for (int im = 0; im < 2; im++) {
                ldsm_x4(ah[im], aAddrH[im] + bo);
                ldsm_x4(al[im], aAddrL[im] + bo);
            }
            #pragma unroll
            for (int jb = 0; jb < 4; jb++) {
                ldsm_x4(bh[jb], bAddrH[jb] + bo);
                ldsm_x4(bl[jb], bAddrL[jb] + bo);
            }

            if (kt + 1 < 48) {
                char* dst = sm + (b ^ 1) * bufBytes;
                *(uint4*)(dst + stoff)           = rah;
                *(uint4*)(dst + TBA + stoff)     = ral;
                *(uint4*)(dst + 2 * TBA + stoff) = rbh;
                *(uint4*)(dst + 3 * TBA + stoff) = rbl;
            }

            #pragma unroll
            for (int im = 0; im < 2; im++)
                #pragma unroll
                for (int jn = 0; jn < 8; jn++) {
                    int jb = jn >> 1, o = (jn & 1) * 2;
                    mma_bf16(acc[im][jn], ah[im], bh[jb][o], bh[jb][o + 1]);
                    mma_bf16(acc[im][jn], ah[im], bl[jb][o], bl[jb][o + 1]);
                    mma_bf16(acc[im][jn], al[im], bh[jb][o], bh[jb][o + 1]);
                }

            __syncthreads();
        }

        if (tid < BM) { rowSum[tid] = 0; colSum[tid] = 0; }
        __syncthreads();

        int rcnt[2][2];  rcnt[0][0] = rcnt[0][1] = rcnt[1][0] = rcnt[1][1] = 0;
        int ccnt[16];
        #pragma unroll
        for (int q = 0; q < 16; q++) ccnt[q] = 0;

        int rbase = wm * 32 + (lane >> 2);
        int cbase = wn * 64 + (lane & 3) * 2;

        #pragma unroll
        for (int im = 0; im < 2; im++) {
            #pragma unroll
            for (int jn = 0; jn < 8; jn++) {
                #pragma unroll
                for (int e4 = 0; e4 < 4; e4++) {
                    int h = e4 >> 1, e = e4 & 1;
                    int gi = i0 + rbase + im * 16 + h * 8;
                    int gj = j0 + cbase + jn * 8 + e;
                    if (diag && gj <= gi) continue;
                    float v = acc[im][jn][e4];
                    int c;
                    if (fabsf(v) >= TAU) c = (v >= 0.0f);
                    else                 c = (exact_dot(X, gi, gj) >= 0.0f);
                    rcnt[im][h] += c;
                    ccnt[jn * 2 + e] += c;
                }
            }
        }
        #pragma unroll
        for (int im = 0; im < 2; im++)
            #pragma unroll
            for (int h = 0; h < 2; h++)
                atomicAdd(&rowSum[rbase + im * 16 + h * 8], rcnt[im][h]);
        #pragma unroll
        for (int jn = 0; jn < 8; jn++)
            #pragma unroll
            for (int e = 0; e < 2; e++)
                atomicAdd(&colSum[cbase + jn * 8 + e], ccnt[jn * 2 + e]);
        __syncthreads();

        if (tid < BM) {
            if (rowSum[tid]) atomicAdd(&g_counts[i0 + tid], rowSum[tid]);
            if (colSum[tid]) atomicAdd(&g_counts[j0 + tid], colSum[tid]);
        }
        __syncthreads();
    }
}

// ---------------------------------------------------------------------------
// 1) dual-pipe GEMM, CTA-level specialization: CTAs 0-147 FFMA2 (fma pipe),
//    CTAs 148-295 HMMA (tensor pipe); bid%148 placement pairs them per SM.
// ---------------------------------------------------------------------------
__global__ __launch_bounds__(256, 2)
void dual_gemm(const float* __restrict__ X) {
    extern __shared__ char sm[];
    if (blockIdx.x < 148) ffma2_engine(X, sm);
    else                  hmma_engine(X, sm);
}

// ---------------------------------------------------------------------------
// 2) grid-wide argmin of counts via packed key atomicMin (first occurrence)
// ---------------------------------------------------------------------------
__global__ void argmin_kernel() {
    int i = blockIdx.x * blockDim.x + threadIdx.x;   // 4096 threads
    int key = g_counts[i] * 4096 + i;
    #pragma unroll
    for (int o = 16; o > 0; o >>= 1)
        key = min(key, __shfl_xor_sync(0xffffffffu, key, o));
    if ((threadIdx.x & 31) == 0) atomicMin(&g_best, key);
}

// ---------------------------------------------------------------------------
// 3) sim[seed][j] for all j + initial mask. warp per j, float4 loads.
// ---------------------------------------------------------------------------
__global__ void seedrow_kernel(const float* __restrict__ X,
                               const int* __restrict__ attn) {
    int gwarp = (blockIdx.x * blockDim.x + threadIdx.x) >> 5;
    int lane  = threadIdx.x & 31;
    if (gwarp >= NPTS) return;
    int seed = blend_seed(g_best, attn);
    const float4* xs = (const float4*)(X + (size_t)seed * DIM);
    const float4* xj = (const float4*)(X + (size_t)gwarp * DIM);
    float p = 0.0f;
    #pragma unroll
    for (int q = 0; q < 6; q++) {
        float4 u = xs[lane + 32 * q], w = xj[lane + 32 * q];
        p += u.x * w.x + u.y * w.y + u.z * w.z + u.w * w.w;
    }
    #pragma unroll
    for (int o = 16; o > 0; o >>= 1) p += __shfl_down_sync(0xffffffffu, p, o);
    if (lane == 0) {
        g_simseed[gwarp] = p;
        g_s[gwarp] = (p >= 0.0f) ? 1 : 0;
    }
}

// ---------------------------------------------------------------------------
// 4) top-100 via bitonic sort on packed 64-bit keys
// ---------------------------------------------------------------------------
__device__ __forceinline__ unsigned ford(float v) {   // monotonic float->uint
    unsigned u = __float_as_uint(v);
    return (u & 0x80000000u) ? ~u : (u | 0x80000000u);
}
__global__ void topk_kernel(const int* __restrict__ attn) {
    __shared__ unsigned long long sk[NPTS];
    int tid = threadIdx.x;   // 1024 threads
    int seed = blend_seed(g_best, attn);
    for (int i = tid; i < NPTS; i += 1024)
        sk[i] = ((unsigned long long)ford(g_simseed[i]) << 32)
              | (unsigned)(NPTS - 1 - i);
    __syncthreads();
    for (int k = 2; k <= NPTS; k <<= 1) {
        for (int j = k >> 1; j > 0; j >>= 1) {
            for (int i = tid; i < NPTS; i += 1024) {
                int ixj = i ^ j;
                if (ixj > i) {
                    unsigned long long k1 = sk[i], k2 = sk[ixj];
                    bool g = (k1 < k2);
                    bool dirDesc = ((i & k) == 0);
                    if (g == dirDesc) { sk[i] = k2; sk[ixj] = k1; }
                }
            }
            __syncthreads();
        }
    }
    unsigned long long k99 = sk[KTOP - 1];
    for (int i = tid; i < NPTS; i += 1024) {
        int s = g_s[i];
        if (i == seed) s = 1;
        unsigned long long ki = ((unsigned long long)ford(g_simseed[i]) << 32)
                              | (unsigned)(NPTS - 1 - i);
        g_s[i] = (ki >= k99) ? s : 0;
    }
}

// ---------------------------------------------------------------------------
// 5) sequential expansion, single warp, float4 loads, register accumulator.
// ---------------------------------------------------------------------------
__global__ void scan_kernel(const float* __restrict__ X) {
    __shared__ int list[KTOP + 32];
    int lane = threadIdx.x;   // 32 threads

    int cnt = 0;
    for (int c = 0; c < NPTS / 32; c++) {
        int idx = c * 32 + lane;
        int val = g_s[idx];
        unsigned m = __ballot_sync(0xffffffffu, val != 0);
        if (val) {
            int pos = cnt + __popc(m & ((1u << lane) - 1));
            if (pos < KTOP + 32) list[pos] = idx;
        }
        cnt += __popc(m);
    }
    int na = (cnt < KTOP + 32) ? cnt : (KTOP + 32);
    __syncwarp();

    float4 v4[6];
    #pragma unroll
    for (int q = 0; q < 6; q++) v4[q] = make_float4(0.f, 0.f, 0.f, 0.f);
    for (int l = 0; l < na; l++) {
        const float4* x = (const float4*)(X + (size_t)list[l] * DIM);
        #pragma unroll
        for (int q = 0; q < 6; q++) {
            float4 u = x[lane + 32 * q];
            v4[q].x += u.x; v4[q].y += u.y; v4[q].z += u.z; v4[q].w += u.w;
        }
    }

    for (int l = 0; l < na; l++) {
        int i = list[l];
        const float4* x = (const float4*)(X + (size_t)i * DIM);
        float4 xr[6];
        float dot = 0.0f;
        #pragma unroll
        for (int q = 0; q < 6; q++) {
            xr[q] = x[lane + 32 * q];
            dot += xr[q].x * v4[q].x + xr[q].y * v4[q].y
                 + xr[q].z * v4[q].z + xr[q].w * v4[q].w;
        }
        #pragma unroll
        for (int o = 16; o > 0; o >>= 1) dot += __shfl_xor_sync(0xffffffffu, dot, o);
        if (dot <= 0.0f) {
            if (lane == 0) g_s[i] = 0;
            #pragma unroll
            for (int q = 0; q < 6; q++) {
                v4[q].x -= xr[q].x; v4[q].y -= xr[q].y;
                v4[q].z -= xr[q].z; v4[q].w -= xr[q].w;
            }
        }
    }
}

// ---------------------------------------------------------------------------
// 6) 8-connected components: in-place min-label propagation to fixpoint.
// ---------------------------------------------------------------------------
__global__ void cc_kernel(float* __restrict__ outp) {
    __shared__ int lab[66 * 66];
    __shared__ int changed;
    const int BIG = NPTS + 1;
    int tid = threadIdx.x;   // 1024 threads

    for (int p = tid; p < 66 * 66; p += 1024) lab[p] = BIG;
    __syncthreads();

    int fgp[4], pos[4];
    #pragma unroll
    for (int q = 0; q < 4; q++) {
        int p = tid + q * 1024;
        int r = p >> 6, c = p & 63;
        pos[q] = (r + 1) * 66 + (c + 1);
        fgp[q] = g_s[p];
        lab[pos[q]] = fgp[q] ? (p + 1) : BIG;
    }
    __syncthreads();

    while (true) {
        if (tid == 0) changed = 0;
        __syncthreads();
        int lc = 0;
        #pragma unroll
        for (int q = 0; q < 4; q++) {
            if (fgp[q]) {
                int pp = pos[q];
                int m = lab[pp];
                m = min(m, lab[pp - 67]); m = min(m, lab[pp - 66]); m = min(m, lab[pp - 65]);
                m = min(m, lab[pp - 1]);                            m = min(m, lab[pp + 1]);
                m = min(m, lab[pp + 65]); m = min(m, lab[pp + 66]); m = min(m, lab[pp + 67]);
                if (m < lab[pp]) { lab[pp] = m; lc = 1; }
            }
        }
        if (lc) changed = 1;
        __syncthreads();
        int done = !changed;
        __syncthreads();
        if (done) break;
    }

    #pragma unroll
    for (int q = 0; q < 4; q++) {
        int p = tid + q * 1024;
        outp[p] = fgp[q] ? (float)lab[pos[q]] : 0.0f;
    }
}

// ---------------------------------------------------------------------------
extern "C" void kernel_launch(void* const* d_in, const int* in_sizes, int n_in,
                              void* d_out, int out_size) {
    const float* X;
    const int*   attn;
    if (n_in >= 2 && in_sizes[0] == 2) {
        attn = (const int*)d_in[0];
        X    = (const float*)d_in[1];
    } else {
        X    = (const float*)d_in[0];
        attn = (const int*)d_in[1];
    }
    float* outp = (float*)d_out;

    cudaFuncSetAttribute(dual_gemm, cudaFuncAttributeMaxDynamicSharedMemorySize, SMEM_DYN);

    convert_split<<<(NPTS * DIM / 4) / 256, 256>>>(X);
    dual_gemm<<<296, 256, SMEM_DYN>>>(X);
    argmin_kernel<<<16, 256>>>();
    seedrow_kernel<<<NPTS / 8, 256>>>(X, attn);
    topk_kernel<<<1, 1024>>>(attn);
    scan_kernel<<<1, 32>>>(X);
    cc_kernel<<<1, 1024>>>(outp);
}